// round 15
// baseline (speedup 1.0000x reference)
#include <cuda_runtime.h>

// Cubic B-spline (de Boor) elementwise evaluation via piecewise power-basis
// polynomials. nt=10 -> 2 cubic pieces split at one threshold. Hot loop
// (champion, locked): dual Horner cubics on the fma pipe + one ternary
// select; zero-mask elided when provably redundant (left piece constant
// coeff == 0 => Horner(0) == 0 exactly). Chip-wide grid-stride interleave,
// float4 streaming __ldcs loads / __stcs stores, 4-deep front-batched loads.
// Grid = 1776 blocks: finer CTA granularity -> overflow waves back-fill SMs
// as early CTAs drain (block-count trend 740 < 1024 < 1184 all confirmed
// monotone on this body; this probes one step further).
//
// Ruled out by experiment (all regressed): 8-deep batching, FSEL coeff
// select, block-contiguous tiling, 32-reg occupancy cap, write-back stores,
// exact-wave grids (740, 1024).

#define KDEG 3
#define MAXM 16

__global__ __launch_bounds__(256)
void bspline_eval_kernel(const float* __restrict__ in,
                         float* __restrict__ out,
                         const float* __restrict__ t,
                         const float* __restrict__ c,
                         int n, int nt)
{
    __shared__ float  s_thr[MAXM];
    __shared__ float4 s_p[MAXM];

    const int numM = nt - 2 * KDEG - 1;   // number of polynomial pieces

    // --- Per-block setup: symbolic de Boor -> power-basis coefficients ---
    if (threadIdx.x < (unsigned)numM && threadIdx.x < MAXM) {
        const int mi = threadIdx.x;
        const int m  = KDEG + mi;

        float d[KDEG + 1][KDEG + 1];
        #pragma unroll
        for (int j = 0; j <= KDEG; ++j) {
            d[j][0] = c[m - KDEG + j];
            #pragma unroll
            for (int q = 1; q <= KDEG; ++q) d[j][q] = 0.0f;
        }

        #pragma unroll
        for (int r = 1; r <= KDEG; ++r) {
            #pragma unroll
            for (int j = KDEG; j >= 1; --j) {
                if (j < r) continue;
                const float left  = t[j + m - KDEG];
                const float right = t[j + 1 + m - r];
                const float denom = right - left;
                if (denom > 0.0f) {
                    const float inv = 1.0f / denom;
                    const float a0  = -left * inv;
                    float diff[KDEG + 1], nd[KDEG + 1];
                    #pragma unroll
                    for (int q = 0; q <= KDEG; ++q) {
                        diff[q] = d[j][q] - d[j - 1][q];
                        nd[q]   = fmaf(a0, diff[q], d[j - 1][q]);
                    }
                    #pragma unroll
                    for (int q = 0; q < KDEG; ++q)
                        nd[q + 1] = fmaf(inv, diff[q], nd[q + 1]);
                    #pragma unroll
                    for (int q = 0; q <= KDEG; ++q) d[j][q] = nd[q];
                } else {
                    #pragma unroll
                    for (int q = 0; q <= KDEG; ++q) d[j][q] = d[j - 1][q];
                }
            }
        }
        s_p[mi] = make_float4(d[KDEG][0], d[KDEG][1], d[KDEG][2], d[KDEG][3]);
        if (mi + 1 < numM) s_thr[mi] = t[KDEG + 1 + mi];
    }
    __syncthreads();

    const int n4 = n >> 2;
    const float4* __restrict__ in4  = reinterpret_cast<const float4*>(in);
    float4* __restrict__       out4 = reinterpret_cast<float4*>(out);
    const int stride = blockDim.x * gridDim.x;
    int i = blockIdx.x * blockDim.x + threadIdx.x;

    if (numM == 2) {
        const float4 pA  = s_p[0];
        const float4 pB  = s_p[1];
        const float  thr = s_thr[0];
        // Zero-mask redundant iff left piece's constant coeff is exactly 0
        // (then Horner at x==0 yields exactly 0) and x==0 selects piece A.
        const bool maskFree = (pA.x == 0.0f) && (thr > 0.0f);

        if (maskFree) {
            for (; i + 3 * stride < n4; i += 4 * stride) {
                float4 v[4];
                #pragma unroll
                for (int b = 0; b < 4; ++b) v[b] = __ldcs(in4 + i + b * stride);
                #pragma unroll
                for (int b = 0; b < 4; ++b) {
                    float* e = reinterpret_cast<float*>(&v[b]);
                    #pragma unroll
                    for (int q = 0; q < 4; ++q) {
                        const float x  = e[q];
                        const float yA = fmaf(fmaf(fmaf(pA.w, x, pA.z), x, pA.y), x, pA.x);
                        const float yB = fmaf(fmaf(fmaf(pB.w, x, pB.z), x, pB.y), x, pB.x);
                        e[q] = (x >= thr) ? yB : yA;
                    }
                }
                #pragma unroll
                for (int b = 0; b < 4; ++b) __stcs(out4 + i + b * stride, v[b]);
            }
            for (; i < n4; i += stride) {
                float4 v = __ldcs(in4 + i);
                float* e = reinterpret_cast<float*>(&v);
                #pragma unroll
                for (int q = 0; q < 4; ++q) {
                    const float x  = e[q];
                    const float yA = fmaf(fmaf(fmaf(pA.w, x, pA.z), x, pA.y), x, pA.x);
                    const float yB = fmaf(fmaf(fmaf(pB.w, x, pB.z), x, pB.y), x, pB.x);
                    e[q] = (x >= thr) ? yB : yA;
                }
                __stcs(out4 + i, v);
            }
            for (int s = (n4 << 2) + blockIdx.x * blockDim.x + threadIdx.x; s < n;
                 s += stride) {
                const float x  = in[s];
                const float yA = fmaf(fmaf(fmaf(pA.w, x, pA.z), x, pA.y), x, pA.x);
                const float yB = fmaf(fmaf(fmaf(pB.w, x, pB.z), x, pB.y), x, pB.x);
                out[s] = (x >= thr) ? yB : yA;
            }
        } else {
            for (; i + 3 * stride < n4; i += 4 * stride) {
                float4 v[4];
                #pragma unroll
                for (int b = 0; b < 4; ++b) v[b] = __ldcs(in4 + i + b * stride);
                #pragma unroll
                for (int b = 0; b < 4; ++b) {
                    float* e = reinterpret_cast<float*>(&v[b]);
                    #pragma unroll
                    for (int q = 0; q < 4; ++q) {
                        const float x  = e[q];
                        const float yA = fmaf(fmaf(fmaf(pA.w, x, pA.z), x, pA.y), x, pA.x);
                        const float yB = fmaf(fmaf(fmaf(pB.w, x, pB.z), x, pB.y), x, pB.x);
                        float y = (x >= thr) ? yB : yA;
                        e[q] = (x == 0.0f) ? 0.0f : y;
                    }
                }
                #pragma unroll
                for (int b = 0; b < 4; ++b) __stcs(out4 + i + b * stride, v[b]);
            }
            for (; i < n4; i += stride) {
                float4 v = __ldcs(in4 + i);
                float* e = reinterpret_cast<float*>(&v);
                #pragma unroll
                for (int q = 0; q < 4; ++q) {
                    const float x  = e[q];
                    const float yA = fmaf(fmaf(fmaf(pA.w, x, pA.z), x, pA.y), x, pA.x);
                    const float yB = fmaf(fmaf(fmaf(pB.w, x, pB.z), x, pB.y), x, pB.x);
                    float y = (x >= thr) ? yB : yA;
                    e[q] = (x == 0.0f) ? 0.0f : y;
                }
                __stcs(out4 + i, v);
            }
            for (int s = (n4 << 2) + blockIdx.x * blockDim.x + threadIdx.x; s < n;
                 s += stride) {
                const float x  = in[s];
                const float yA = fmaf(fmaf(fmaf(pA.w, x, pA.z), x, pA.y), x, pA.x);
                const float yB = fmaf(fmaf(fmaf(pB.w, x, pB.z), x, pB.y), x, pB.x);
                float y = (x >= thr) ? yB : yA;
                out[s] = (x == 0.0f) ? 0.0f : y;
            }
        }
    } else {
        // ---- Generic path: smem threshold scan + coefficient lookup ----
        const int nth = numM - 1;
        for (; i < n4; i += stride) {
            float4 v = __ldcs(in4 + i);
            float* e = reinterpret_cast<float*>(&v);
            #pragma unroll
            for (int q = 0; q < 4; ++q) {
                const float x = e[q];
                int mi = 0;
                for (int b = 0; b < nth; ++b) mi += (x >= s_thr[b]) ? 1 : 0;
                const float4 p = s_p[mi];
                float y = fmaf(fmaf(fmaf(p.w, x, p.z), x, p.y), x, p.x);
                e[q] = (x == 0.0f) ? 0.0f : y;
            }
            __stcs(out4 + i, v);
        }
        for (int s = (n4 << 2) + blockIdx.x * blockDim.x + threadIdx.x; s < n;
             s += stride) {
            const float x = in[s];
            int mi = 0;
            for (int b = 0; b < nth; ++b) mi += (x >= s_thr[b]) ? 1 : 0;
            const float4 p = s_p[mi];
            float y = fmaf(fmaf(fmaf(p.w, x, p.z), x, p.y), x, p.x);
            out[s] = (x == 0.0f) ? 0.0f : y;
        }
    }
}

extern "C" void kernel_launch(void* const* d_in, const int* in_sizes, int n_in,
                              void* d_out, int out_size)
{
    const float* imgs = (const float*)d_in[0];
    const float* t    = (const float*)d_in[1];
    const float* c    = (const float*)d_in[2];
    float* out        = (float*)d_out;

    const int n  = in_sizes[0];
    const int nt = in_sizes[1];

    const int threads = 256;
    // Block-count gradient probe: 740 (72.8) < 1024 (70.1) < 1184 (68.35)
    // -> try 1776 (12/SM nominal, ~2.4 queued waves of 7-resident CTAs).
    int blocks = 1776;
    int needed = (n / 4 + threads - 1) / threads;
    if (needed < 1) needed = 1;
    if (blocks > needed) blocks = needed;

    bspline_eval_kernel<<<blocks, threads>>>(imgs, out, t, c, n, nt);
}

// round 16
// speedup vs baseline: 1.0395x; 1.0395x over previous
#include <cuda_runtime.h>

// Cubic B-spline (de Boor) elementwise evaluation via piecewise power-basis
// polynomials. nt=10 -> 2 cubic pieces split at one threshold. Hot loop
// (champion, locked): dual Horner cubics on the fma pipe + one ternary
// select; zero-mask elided when provably redundant (left piece constant
// coeff == 0 => Horner(0) == 0 exactly). Chip-wide grid-stride interleave,
// float4 streaming __ldcs loads / __stcs stores, 4-deep front-batched loads.
// Grid = 2368 blocks (16/SM nominal): block-count gradient is monotone
// (740: 72.8 > 1024: 70.1 > 1184: 68.35 > 1776: 68.26 harness; ncu 65.9 >
// 66.6 > 64.4 > 59.97) -- finer CTA granularity back-fills SM L1tex queues
// through the kernel tail.
//
// Ruled out by experiment (all regressed): 8-deep batching, FSEL coeff
// select, block-contiguous tiling, 32-reg occupancy cap, write-back stores,
// exact-wave grids.

#define KDEG 3
#define MAXM 16

__global__ __launch_bounds__(256)
void bspline_eval_kernel(const float* __restrict__ in,
                         float* __restrict__ out,
                         const float* __restrict__ t,
                         const float* __restrict__ c,
                         int n, int nt)
{
    __shared__ float  s_thr[MAXM];
    __shared__ float4 s_p[MAXM];

    const int numM = nt - 2 * KDEG - 1;   // number of polynomial pieces

    // --- Per-block setup: symbolic de Boor -> power-basis coefficients ---
    if (threadIdx.x < (unsigned)numM && threadIdx.x < MAXM) {
        const int mi = threadIdx.x;
        const int m  = KDEG + mi;

        float d[KDEG + 1][KDEG + 1];
        #pragma unroll
        for (int j = 0; j <= KDEG; ++j) {
            d[j][0] = c[m - KDEG + j];
            #pragma unroll
            for (int q = 1; q <= KDEG; ++q) d[j][q] = 0.0f;
        }

        #pragma unroll
        for (int r = 1; r <= KDEG; ++r) {
            #pragma unroll
            for (int j = KDEG; j >= 1; --j) {
                if (j < r) continue;
                const float left  = t[j + m - KDEG];
                const float right = t[j + 1 + m - r];
                const float denom = right - left;
                if (denom > 0.0f) {
                    const float inv = 1.0f / denom;
                    const float a0  = -left * inv;
                    float diff[KDEG + 1], nd[KDEG + 1];
                    #pragma unroll
                    for (int q = 0; q <= KDEG; ++q) {
                        diff[q] = d[j][q] - d[j - 1][q];
                        nd[q]   = fmaf(a0, diff[q], d[j - 1][q]);
                    }
                    #pragma unroll
                    for (int q = 0; q < KDEG; ++q)
                        nd[q + 1] = fmaf(inv, diff[q], nd[q + 1]);
                    #pragma unroll
                    for (int q = 0; q <= KDEG; ++q) d[j][q] = nd[q];
                } else {
                    #pragma unroll
                    for (int q = 0; q <= KDEG; ++q) d[j][q] = d[j - 1][q];
                }
            }
        }
        s_p[mi] = make_float4(d[KDEG][0], d[KDEG][1], d[KDEG][2], d[KDEG][3]);
        if (mi + 1 < numM) s_thr[mi] = t[KDEG + 1 + mi];
    }
    __syncthreads();

    const int n4 = n >> 2;
    const float4* __restrict__ in4  = reinterpret_cast<const float4*>(in);
    float4* __restrict__       out4 = reinterpret_cast<float4*>(out);
    const int stride = blockDim.x * gridDim.x;
    int i = blockIdx.x * blockDim.x + threadIdx.x;

    if (numM == 2) {
        const float4 pA  = s_p[0];
        const float4 pB  = s_p[1];
        const float  thr = s_thr[0];
        // Zero-mask redundant iff left piece's constant coeff is exactly 0
        // (then Horner at x==0 yields exactly 0) and x==0 selects piece A.
        const bool maskFree = (pA.x == 0.0f) && (thr > 0.0f);

        if (maskFree) {
            for (; i + 3 * stride < n4; i += 4 * stride) {
                float4 v[4];
                #pragma unroll
                for (int b = 0; b < 4; ++b) v[b] = __ldcs(in4 + i + b * stride);
                #pragma unroll
                for (int b = 0; b < 4; ++b) {
                    float* e = reinterpret_cast<float*>(&v[b]);
                    #pragma unroll
                    for (int q = 0; q < 4; ++q) {
                        const float x  = e[q];
                        const float yA = fmaf(fmaf(fmaf(pA.w, x, pA.z), x, pA.y), x, pA.x);
                        const float yB = fmaf(fmaf(fmaf(pB.w, x, pB.z), x, pB.y), x, pB.x);
                        e[q] = (x >= thr) ? yB : yA;
                    }
                }
                #pragma unroll
                for (int b = 0; b < 4; ++b) __stcs(out4 + i + b * stride, v[b]);
            }
            for (; i < n4; i += stride) {
                float4 v = __ldcs(in4 + i);
                float* e = reinterpret_cast<float*>(&v);
                #pragma unroll
                for (int q = 0; q < 4; ++q) {
                    const float x  = e[q];
                    const float yA = fmaf(fmaf(fmaf(pA.w, x, pA.z), x, pA.y), x, pA.x);
                    const float yB = fmaf(fmaf(fmaf(pB.w, x, pB.z), x, pB.y), x, pB.x);
                    e[q] = (x >= thr) ? yB : yA;
                }
                __stcs(out4 + i, v);
            }
            for (int s = (n4 << 2) + blockIdx.x * blockDim.x + threadIdx.x; s < n;
                 s += stride) {
                const float x  = in[s];
                const float yA = fmaf(fmaf(fmaf(pA.w, x, pA.z), x, pA.y), x, pA.x);
                const float yB = fmaf(fmaf(fmaf(pB.w, x, pB.z), x, pB.y), x, pB.x);
                out[s] = (x >= thr) ? yB : yA;
            }
        } else {
            for (; i + 3 * stride < n4; i += 4 * stride) {
                float4 v[4];
                #pragma unroll
                for (int b = 0; b < 4; ++b) v[b] = __ldcs(in4 + i + b * stride);
                #pragma unroll
                for (int b = 0; b < 4; ++b) {
                    float* e = reinterpret_cast<float*>(&v[b]);
                    #pragma unroll
                    for (int q = 0; q < 4; ++q) {
                        const float x  = e[q];
                        const float yA = fmaf(fmaf(fmaf(pA.w, x, pA.z), x, pA.y), x, pA.x);
                        const float yB = fmaf(fmaf(fmaf(pB.w, x, pB.z), x, pB.y), x, pB.x);
                        float y = (x >= thr) ? yB : yA;
                        e[q] = (x == 0.0f) ? 0.0f : y;
                    }
                }
                #pragma unroll
                for (int b = 0; b < 4; ++b) __stcs(out4 + i + b * stride, v[b]);
            }
            for (; i < n4; i += stride) {
                float4 v = __ldcs(in4 + i);
                float* e = reinterpret_cast<float*>(&v);
                #pragma unroll
                for (int q = 0; q < 4; ++q) {
                    const float x  = e[q];
                    const float yA = fmaf(fmaf(fmaf(pA.w, x, pA.z), x, pA.y), x, pA.x);
                    const float yB = fmaf(fmaf(fmaf(pB.w, x, pB.z), x, pB.y), x, pB.x);
                    float y = (x >= thr) ? yB : yA;
                    e[q] = (x == 0.0f) ? 0.0f : y;
                }
                __stcs(out4 + i, v);
            }
            for (int s = (n4 << 2) + blockIdx.x * blockDim.x + threadIdx.x; s < n;
                 s += stride) {
                const float x  = in[s];
                const float yA = fmaf(fmaf(fmaf(pA.w, x, pA.z), x, pA.y), x, pA.x);
                const float yB = fmaf(fmaf(fmaf(pB.w, x, pB.z), x, pB.y), x, pB.x);
                float y = (x >= thr) ? yB : yA;
                out[s] = (x == 0.0f) ? 0.0f : y;
            }
        }
    } else {
        // ---- Generic path: smem threshold scan + coefficient lookup ----
        const int nth = numM - 1;
        for (; i < n4; i += stride) {
            float4 v = __ldcs(in4 + i);
            float* e = reinterpret_cast<float*>(&v);
            #pragma unroll
            for (int q = 0; q < 4; ++q) {
                const float x = e[q];
                int mi = 0;
                for (int b = 0; b < nth; ++b) mi += (x >= s_thr[b]) ? 1 : 0;
                const float4 p = s_p[mi];
                float y = fmaf(fmaf(fmaf(p.w, x, p.z), x, p.y), x, p.x);
                e[q] = (x == 0.0f) ? 0.0f : y;
            }
            __stcs(out4 + i, v);
        }
        for (int s = (n4 << 2) + blockIdx.x * blockDim.x + threadIdx.x; s < n;
             s += stride) {
            const float x = in[s];
            int mi = 0;
            for (int b = 0; b < nth; ++b) mi += (x >= s_thr[b]) ? 1 : 0;
            const float4 p = s_p[mi];
            float y = fmaf(fmaf(fmaf(p.w, x, p.z), x, p.y), x, p.x);
            out[s] = (x == 0.0f) ? 0.0f : y;
        }
    }
}

extern "C" void kernel_launch(void* const* d_in, const int* in_sizes, int n_in,
                              void* d_out, int out_size)
{
    const float* imgs = (const float*)d_in[0];
    const float* t    = (const float*)d_in[1];
    const float* c    = (const float*)d_in[2];
    float* out        = (float*)d_out;

    const int n  = in_sizes[0];
    const int nt = in_sizes[1];

    const int threads = 256;
    // Block-count gradient: 740 -> 1024 -> 1184 -> 1776 all improved;
    // probe 2368 (16/SM nominal).
    int blocks = 2368;
    int needed = (n / 4 + threads - 1) / threads;
    if (needed < 1) needed = 1;
    if (blocks > needed) blocks = needed;

    bspline_eval_kernel<<<blocks, threads>>>(imgs, out, t, c, n, nt);
}

// round 17
// speedup vs baseline: 1.0405x; 1.0010x over previous
#include <cuda_runtime.h>

// Cubic B-spline (de Boor) elementwise evaluation via piecewise power-basis
// polynomials. nt=10 -> 2 cubic pieces split at one threshold. Hot loop
// (champion, locked): dual Horner cubics on the fma pipe + one ternary
// select; zero-mask elided when provably redundant (left piece constant
// coeff == 0 => Horner(0) == 0 exactly). Chip-wide grid-stride interleave,
// float4 streaming __ldcs loads / __stcs stores, 4-deep front-batched loads.
// Grid = 3552 blocks (24/SM nominal): block-count gradient is monotone
// (740: 72.8 > 1024: 70.1 > 1184: 68.35 > 1776: 68.26 > 2368: 65.66
// harness; DRAM% 65.5 -> 75.5 over the same series) -- finer CTA
// granularity back-fills SM L1tex queues through the kernel tail.
//
// Ruled out by experiment (all regressed): 8-deep batching, FSEL coeff
// select, block-contiguous tiling, 32-reg occupancy cap, write-back stores,
// exact-wave grids.

#define KDEG 3
#define MAXM 16

__global__ __launch_bounds__(256)
void bspline_eval_kernel(const float* __restrict__ in,
                         float* __restrict__ out,
                         const float* __restrict__ t,
                         const float* __restrict__ c,
                         int n, int nt)
{
    __shared__ float  s_thr[MAXM];
    __shared__ float4 s_p[MAXM];

    const int numM = nt - 2 * KDEG - 1;   // number of polynomial pieces

    // --- Per-block setup: symbolic de Boor -> power-basis coefficients ---
    if (threadIdx.x < (unsigned)numM && threadIdx.x < MAXM) {
        const int mi = threadIdx.x;
        const int m  = KDEG + mi;

        float d[KDEG + 1][KDEG + 1];
        #pragma unroll
        for (int j = 0; j <= KDEG; ++j) {
            d[j][0] = c[m - KDEG + j];
            #pragma unroll
            for (int q = 1; q <= KDEG; ++q) d[j][q] = 0.0f;
        }

        #pragma unroll
        for (int r = 1; r <= KDEG; ++r) {
            #pragma unroll
            for (int j = KDEG; j >= 1; --j) {
                if (j < r) continue;
                const float left  = t[j + m - KDEG];
                const float right = t[j + 1 + m - r];
                const float denom = right - left;
                if (denom > 0.0f) {
                    const float inv = 1.0f / denom;
                    const float a0  = -left * inv;
                    float diff[KDEG + 1], nd[KDEG + 1];
                    #pragma unroll
                    for (int q = 0; q <= KDEG; ++q) {
                        diff[q] = d[j][q] - d[j - 1][q];
                        nd[q]   = fmaf(a0, diff[q], d[j - 1][q]);
                    }
                    #pragma unroll
                    for (int q = 0; q < KDEG; ++q)
                        nd[q + 1] = fmaf(inv, diff[q], nd[q + 1]);
                    #pragma unroll
                    for (int q = 0; q <= KDEG; ++q) d[j][q] = nd[q];
                } else {
                    #pragma unroll
                    for (int q = 0; q <= KDEG; ++q) d[j][q] = d[j - 1][q];
                }
            }
        }
        s_p[mi] = make_float4(d[KDEG][0], d[KDEG][1], d[KDEG][2], d[KDEG][3]);
        if (mi + 1 < numM) s_thr[mi] = t[KDEG + 1 + mi];
    }
    __syncthreads();

    const int n4 = n >> 2;
    const float4* __restrict__ in4  = reinterpret_cast<const float4*>(in);
    float4* __restrict__       out4 = reinterpret_cast<float4*>(out);
    const int stride = blockDim.x * gridDim.x;
    int i = blockIdx.x * blockDim.x + threadIdx.x;

    if (numM == 2) {
        const float4 pA  = s_p[0];
        const float4 pB  = s_p[1];
        const float  thr = s_thr[0];
        // Zero-mask redundant iff left piece's constant coeff is exactly 0
        // (then Horner at x==0 yields exactly 0) and x==0 selects piece A.
        const bool maskFree = (pA.x == 0.0f) && (thr > 0.0f);

        if (maskFree) {
            for (; i + 3 * stride < n4; i += 4 * stride) {
                float4 v[4];
                #pragma unroll
                for (int b = 0; b < 4; ++b) v[b] = __ldcs(in4 + i + b * stride);
                #pragma unroll
                for (int b = 0; b < 4; ++b) {
                    float* e = reinterpret_cast<float*>(&v[b]);
                    #pragma unroll
                    for (int q = 0; q < 4; ++q) {
                        const float x  = e[q];
                        const float yA = fmaf(fmaf(fmaf(pA.w, x, pA.z), x, pA.y), x, pA.x);
                        const float yB = fmaf(fmaf(fmaf(pB.w, x, pB.z), x, pB.y), x, pB.x);
                        e[q] = (x >= thr) ? yB : yA;
                    }
                }
                #pragma unroll
                for (int b = 0; b < 4; ++b) __stcs(out4 + i + b * stride, v[b]);
            }
            for (; i < n4; i += stride) {
                float4 v = __ldcs(in4 + i);
                float* e = reinterpret_cast<float*>(&v);
                #pragma unroll
                for (int q = 0; q < 4; ++q) {
                    const float x  = e[q];
                    const float yA = fmaf(fmaf(fmaf(pA.w, x, pA.z), x, pA.y), x, pA.x);
                    const float yB = fmaf(fmaf(fmaf(pB.w, x, pB.z), x, pB.y), x, pB.x);
                    e[q] = (x >= thr) ? yB : yA;
                }
                __stcs(out4 + i, v);
            }
            for (int s = (n4 << 2) + blockIdx.x * blockDim.x + threadIdx.x; s < n;
                 s += stride) {
                const float x  = in[s];
                const float yA = fmaf(fmaf(fmaf(pA.w, x, pA.z), x, pA.y), x, pA.x);
                const float yB = fmaf(fmaf(fmaf(pB.w, x, pB.z), x, pB.y), x, pB.x);
                out[s] = (x >= thr) ? yB : yA;
            }
        } else {
            for (; i + 3 * stride < n4; i += 4 * stride) {
                float4 v[4];
                #pragma unroll
                for (int b = 0; b < 4; ++b) v[b] = __ldcs(in4 + i + b * stride);
                #pragma unroll
                for (int b = 0; b < 4; ++b) {
                    float* e = reinterpret_cast<float*>(&v[b]);
                    #pragma unroll
                    for (int q = 0; q < 4; ++q) {
                        const float x  = e[q];
                        const float yA = fmaf(fmaf(fmaf(pA.w, x, pA.z), x, pA.y), x, pA.x);
                        const float yB = fmaf(fmaf(fmaf(pB.w, x, pB.z), x, pB.y), x, pB.x);
                        float y = (x >= thr) ? yB : yA;
                        e[q] = (x == 0.0f) ? 0.0f : y;
                    }
                }
                #pragma unroll
                for (int b = 0; b < 4; ++b) __stcs(out4 + i + b * stride, v[b]);
            }
            for (; i < n4; i += stride) {
                float4 v = __ldcs(in4 + i);
                float* e = reinterpret_cast<float*>(&v);
                #pragma unroll
                for (int q = 0; q < 4; ++q) {
                    const float x  = e[q];
                    const float yA = fmaf(fmaf(fmaf(pA.w, x, pA.z), x, pA.y), x, pA.x);
                    const float yB = fmaf(fmaf(fmaf(pB.w, x, pB.z), x, pB.y), x, pB.x);
                    float y = (x >= thr) ? yB : yA;
                    e[q] = (x == 0.0f) ? 0.0f : y;
                }
                __stcs(out4 + i, v);
            }
            for (int s = (n4 << 2) + blockIdx.x * blockDim.x + threadIdx.x; s < n;
                 s += stride) {
                const float x  = in[s];
                const float yA = fmaf(fmaf(fmaf(pA.w, x, pA.z), x, pA.y), x, pA.x);
                const float yB = fmaf(fmaf(fmaf(pB.w, x, pB.z), x, pB.y), x, pB.x);
                float y = (x >= thr) ? yB : yA;
                out[s] = (x == 0.0f) ? 0.0f : y;
            }
        }
    } else {
        // ---- Generic path: smem threshold scan + coefficient lookup ----
        const int nth = numM - 1;
        for (; i < n4; i += stride) {
            float4 v = __ldcs(in4 + i);
            float* e = reinterpret_cast<float*>(&v);
            #pragma unroll
            for (int q = 0; q < 4; ++q) {
                const float x = e[q];
                int mi = 0;
                for (int b = 0; b < nth; ++b) mi += (x >= s_thr[b]) ? 1 : 0;
                const float4 p = s_p[mi];
                float y = fmaf(fmaf(fmaf(p.w, x, p.z), x, p.y), x, p.x);
                e[q] = (x == 0.0f) ? 0.0f : y;
            }
            __stcs(out4 + i, v);
        }
        for (int s = (n4 << 2) + blockIdx.x * blockDim.x + threadIdx.x; s < n;
             s += stride) {
            const float x = in[s];
            int mi = 0;
            for (int b = 0; b < nth; ++b) mi += (x >= s_thr[b]) ? 1 : 0;
            const float4 p = s_p[mi];
            float y = fmaf(fmaf(fmaf(p.w, x, p.z), x, p.y), x, p.x);
            out[s] = (x == 0.0f) ? 0.0f : y;
        }
    }
}

extern "C" void kernel_launch(void* const* d_in, const int* in_sizes, int n_in,
                              void* d_out, int out_size)
{
    const float* imgs = (const float*)d_in[0];
    const float* t    = (const float*)d_in[1];
    const float* c    = (const float*)d_in[2];
    float* out        = (float*)d_out;

    const int n  = in_sizes[0];
    const int nt = in_sizes[1];

    const int threads = 256;
    // Block-count gradient: 740 -> 1024 -> 1184 -> 1776 -> 2368 all
    // improved; probe 3552 (24/SM nominal).
    int blocks = 3552;
    int needed = (n / 4 + threads - 1) / threads;
    if (needed < 1) needed = 1;
    if (blocks > needed) blocks = needed;

    bspline_eval_kernel<<<blocks, threads>>>(imgs, out, t, c, n, nt);
}